// round 4
// baseline (speedup 1.0000x reference)
#include <cuda_runtime.h>
#include <cuda_bf16.h>
#include <stdint.h>

// Problem constants
#define N 4096
#define D 1024
#define NCLS 128

// GEMM tiling
#define BM 128
#define BN 128
#define BK 32
#define SLD 40   // shared stride in bf16 elements (20 words) -> conflict-free frag loads

// Scratch (allocation-free: __device__ globals)
static __device__ __align__(16) __nv_bfloat16 g_embn[N * D]; // normalized embeddings, bf16
static __device__ float g_rowsum[N];             // sum over negatives of exp(S_ij)
static __device__ float g_posval[N];             // S[i, first_pos[i]] (0 if none)
static __device__ int   g_firstpos[N];           // -1 if no positive
static __device__ int   g_cnt[NCLS];             // class counts
static __device__ int   g_y[N];                  // decoded int labels

// ---------------------------------------------------------------------------
// Kernel 1: per-row L2 normalize, write bf16
// ---------------------------------------------------------------------------
__global__ void k_norm(const float* __restrict__ in) {
    int row = blockIdx.x;
    int t = threadIdx.x;           // 256 threads
    int lane = t & 31, warp = t >> 5;

    float v[4];
#pragma unroll
    for (int k = 0; k < 4; k++) v[k] = in[row * D + t + 256 * k];

    float ss = v[0]*v[0] + v[1]*v[1] + v[2]*v[2] + v[3]*v[3];
#pragma unroll
    for (int o = 16; o > 0; o >>= 1) ss += __shfl_down_sync(0xffffffffu, ss, o);

    __shared__ float w[8];
    if (lane == 0) w[warp] = ss;
    __syncthreads();
    if (t == 0) {
        float tot = 0.f;
#pragma unroll
        for (int i = 0; i < 8; i++) tot += w[i];
        w[0] = 1.0f / fmaxf(sqrtf(tot), 1e-8f);
    }
    __syncthreads();
    float inv = w[0];
#pragma unroll
    for (int k = 0; k < 4; k++)
        g_embn[row * D + t + 256 * k] = __float2bfloat16(v[k] * inv);
}

// ---------------------------------------------------------------------------
// Kernel 2: label decode (int32 vs int64, detected from data), class counts,
// first-positive per row, zero accumulators (re-zeroed every graph replay).
//
// Dtype detection: read buffer as int32[4096] (16KB, safe under either dtype
// since element count is 4096 either way). If the data is little-endian int64
// with values in [0,128), every odd 32-bit word of the first 4096 is zero.
// Under int32 data (uniform labels 0..127), P(all 2048 odd words zero) ~ 0.
// ---------------------------------------------------------------------------
__global__ void k_meta(const int* __restrict__ yraw) {
    __shared__ int sy[N];
    __shared__ int j0s[NCLS], j1s[NCLS];
    __shared__ int oddnz;
    int t = threadIdx.x;           // 256 threads

    if (t == 0) oddnz = 0;
    __syncthreads();
    int local = 0;
    for (int i = t; i < 2048; i += 256)
        if (yraw[2 * i + 1] != 0) local = 1;
    if (local) atomicOr(&oddnz, 1);
    __syncthreads();
    const bool is64 = (oddnz == 0);

    for (int i = t; i < N; i += 256) {
        int v = is64 ? yraw[2 * i] : yraw[i];
        sy[i] = v;
        g_y[i] = v;
    }
    __syncthreads();

    if (t < NCLS) {
        int c = t, cnt = 0, j0 = -1, j1 = -1;
        for (int i = 0; i < N; i++) {
            if (sy[i] == c) {
                cnt++;
                if (j0 < 0) j0 = i;
                else if (j1 < 0) j1 = i;
            }
        }
        g_cnt[c] = cnt; j0s[c] = j0; j1s[c] = j1;
    }
    __syncthreads();

    for (int i = t; i < N; i += 256) {
        int c = sy[i];
        g_firstpos[i] = (j0s[c] == i) ? j1s[c] : j0s[c];
        g_rowsum[i] = 0.0f;
        g_posval[i] = 0.0f;
    }
}

// ---------------------------------------------------------------------------
// Kernel 3: fused GEMM (cos = En·Enᵀ) + epilogue (mask, exp, row-reduce, pos)
// blockDim 256 (8 warps, 4x2 warp grid; warp tile 32x64)
// ---------------------------------------------------------------------------
__device__ __forceinline__ void mma16816(float c[4], const uint32_t a[4], const uint32_t b[2]) {
    asm volatile(
        "mma.sync.aligned.m16n8k16.row.col.f32.bf16.bf16.f32 "
        "{%0,%1,%2,%3}, {%4,%5,%6,%7}, {%8,%9}, {%0,%1,%2,%3};"
        : "+f"(c[0]), "+f"(c[1]), "+f"(c[2]), "+f"(c[3])
        : "r"(a[0]), "r"(a[1]), "r"(a[2]), "r"(a[3]), "r"(b[0]), "r"(b[1]));
}

__global__ void __launch_bounds__(256, 2) k_gemm() {
    __shared__ alignas(16) __nv_bfloat16 As[BM * SLD];
    __shared__ alignas(16) __nv_bfloat16 Bs[BN * SLD];
    __shared__ int ys_r[BM], ys_c[BN], fps[BM];
    __shared__ float rowacc[BM];

    const int tid = threadIdx.x;
    const int br = blockIdx.y, bc = blockIdx.x;
    const int warp = tid >> 5, lane = tid & 31;
    const int wm = warp & 3, wn = warp >> 2;      // 4 warps along M, 2 along N
    const int g = lane >> 2, t4 = lane & 3;

    if (tid < 128) {
        ys_r[tid] = g_y[br * BM + tid];
        ys_c[tid] = g_y[bc * BN + tid];
        fps[tid]  = g_firstpos[br * BM + tid];
        rowacc[tid] = 0.0f;
    }

    float acc[2][8][4];
#pragma unroll
    for (int i = 0; i < 2; i++)
#pragma unroll
        for (int j = 0; j < 8; j++)
#pragma unroll
            for (int e = 0; e < 4; e++) acc[i][j][e] = 0.0f;

    // global load indexing: 512 uint4 per tile, 2 per thread
    const int li0 = tid, li1 = tid + 256;
    const int r0 = li0 >> 2, c0 = (li0 & 3) * 8;
    const int r1 = li1 >> 2, c1 = (li1 & 3) * 8;
    const __nv_bfloat16* gA = g_embn + (size_t)(br * BM) * D;
    const __nv_bfloat16* gB = g_embn + (size_t)(bc * BN) * D;

    for (int k0 = 0; k0 < D; k0 += BK) {
        uint4 a0 = *(const uint4*)(gA + (size_t)r0 * D + k0 + c0);
        uint4 a1 = *(const uint4*)(gA + (size_t)r1 * D + k0 + c1);
        uint4 b0 = *(const uint4*)(gB + (size_t)r0 * D + k0 + c0);
        uint4 b1 = *(const uint4*)(gB + (size_t)r1 * D + k0 + c1);
        __syncthreads();
        *(uint4*)(As + r0 * SLD + c0) = a0;
        *(uint4*)(As + r1 * SLD + c1) = a1;
        *(uint4*)(Bs + r0 * SLD + c0) = b0;
        *(uint4*)(Bs + r1 * SLD + c1) = b1;
        __syncthreads();

        const uint32_t* Aw = (const uint32_t*)As;   // word stride 20/row
        const uint32_t* Bw = (const uint32_t*)Bs;
#pragma unroll
        for (int kk = 0; kk < 2; kk++) {
            const int kw = kk * 8;   // 16 bf16 = 8 words
            uint32_t af[2][4], bf[8][2];
#pragma unroll
            for (int mf = 0; mf < 2; mf++) {
                int r = wm * 32 + mf * 16 + g;
                af[mf][0] = Aw[r * 20 + kw + t4];
                af[mf][1] = Aw[(r + 8) * 20 + kw + t4];
                af[mf][2] = Aw[r * 20 + kw + t4 + 4];
                af[mf][3] = Aw[(r + 8) * 20 + kw + t4 + 4];
            }
#pragma unroll
            for (int nf = 0; nf < 8; nf++) {
                int n = wn * 64 + nf * 8 + g;
                bf[nf][0] = Bw[n * 20 + kw + t4];
                bf[nf][1] = Bw[n * 20 + kw + t4 + 4];
            }
#pragma unroll
            for (int mf = 0; mf < 2; mf++)
#pragma unroll
                for (int nf = 0; nf < 8; nf++)
                    mma16816(acc[mf][nf], af[mf], bf[nf]);
        }
    }

    // ---- epilogue: S = (cos+1)*0.25; mask by class; exp; per-row reduce ----
#pragma unroll
    for (int mf = 0; mf < 2; mf++) {
#pragma unroll
        for (int h = 0; h < 2; h++) {
            const int lr = wm * 32 + mf * 16 + h * 8 + g;
            const int yi = ys_r[lr];
            const int fpi = fps[lr];
            const int gi = br * BM + lr;
            float sum = 0.0f;
#pragma unroll
            for (int nf = 0; nf < 8; nf++) {
#pragma unroll
                for (int e = 0; e < 2; e++) {
                    const int lc = wn * 64 + nf * 8 + t4 * 2 + e;
                    const float S = (acc[mf][nf][h * 2 + e] + 1.0f) * 0.25f;
                    if (ys_c[lc] != yi) sum += __expf(S);
                    if (bc * BN + lc == fpi) g_posval[gi] = S;  // unique writer
                }
            }
            sum += __shfl_xor_sync(0xffffffffu, sum, 1);
            sum += __shfl_xor_sync(0xffffffffu, sum, 2);
            if (t4 == 0) atomicAdd(&rowacc[lr], sum);
        }
    }
    __syncthreads();
    if (tid < 128) atomicAdd(&g_rowsum[br * BM + tid], rowacc[tid]);
}

// ---------------------------------------------------------------------------
// Kernel 4: final per-row lse and scalar reduce
// lse_i = log(exp(pv) + rowsum + (8190 - num_neg)); num_neg = N - cnt[y_i]
// ---------------------------------------------------------------------------
__global__ void k_final(float* __restrict__ out) {
    int t = threadIdx.x;           // 1024 threads
    int lane = t & 31, warp = t >> 5;
    float local = 0.0f;
    for (int i = t; i < N; i += 1024) {
        float pv = g_posval[i];
        int cnt = g_cnt[g_y[i]];
        float zeros = (float)(2 * N - 2 - (N - cnt));  // 8190 - num_neg = 4094 + cnt
        float tot = expf(pv) + g_rowsum[i] + zeros;
        local += logf(tot) - pv;
    }
#pragma unroll
    for (int o = 16; o > 0; o >>= 1) local += __shfl_down_sync(0xffffffffu, local, o);
    __shared__ float red[32];
    if (lane == 0) red[warp] = local;
    __syncthreads();
    if (t < 32) {
        float v = red[t];
#pragma unroll
        for (int o = 16; o > 0; o >>= 1) v += __shfl_down_sync(0xffffffffu, v, o);
        if (t == 0) out[0] = v * (1.0f / (float)N);
    }
}

// ---------------------------------------------------------------------------
extern "C" void kernel_launch(void* const* d_in, const int* in_sizes, int n_in,
                              void* d_out, int out_size) {
    const float* emb = (const float*)d_in[0];
    const int* yraw = (const int*)d_in[1];   // int32 or int64; k_meta detects
    float* out = (float*)d_out;

    k_norm<<<N, 256>>>(emb);
    k_meta<<<1, 256>>>(yraw);
    k_gemm<<<dim3(N / BN, N / BM), 256>>>();
    k_final<<<1, 1024>>>(out);
}

// round 5
// speedup vs baseline: 1.3462x; 1.3462x over previous
#include <cuda_runtime.h>
#include <cuda_bf16.h>
#include <stdint.h>

// Problem constants
#define N 4096
#define D 1024
#define NCLS 128

// GEMM tiling
#define BM 128
#define BN 128
#define BK 32
#define NT (N / BM)         // 32 tiles per dim
#define NBLK (NT * (NT + 1) / 2)   // 528 upper-triangular block tiles
#define SLD 40   // shared stride in bf16 elements (20 words) -> conflict-free frag loads

// Scratch (allocation-free: __device__ globals)
static __device__ __align__(16) __nv_bfloat16 g_embn[N * D]; // normalized embeddings, bf16
static __device__ float g_rowsum[N];             // sum over negatives of exp(S_ij)
static __device__ float g_posval[N];             // S[i, first_pos[i]] (0 if none)
static __device__ int   g_firstpos[N];           // -1 if no positive
static __device__ int   g_cnt[NCLS];             // class counts
static __device__ int   g_y[N];                  // decoded int labels

// ---------------------------------------------------------------------------
// Kernel 1: per-row L2 normalize, write bf16
// ---------------------------------------------------------------------------
__global__ void k_norm(const float* __restrict__ in) {
    int row = blockIdx.x;
    int t = threadIdx.x;           // 256 threads
    int lane = t & 31, warp = t >> 5;

    float v[4];
#pragma unroll
    for (int k = 0; k < 4; k++) v[k] = in[row * D + t + 256 * k];

    float ss = v[0]*v[0] + v[1]*v[1] + v[2]*v[2] + v[3]*v[3];
#pragma unroll
    for (int o = 16; o > 0; o >>= 1) ss += __shfl_down_sync(0xffffffffu, ss, o);

    __shared__ float w[8];
    if (lane == 0) w[warp] = ss;
    __syncthreads();
    if (t == 0) {
        float tot = 0.f;
#pragma unroll
        for (int i = 0; i < 8; i++) tot += w[i];
        w[0] = 1.0f / fmaxf(sqrtf(tot), 1e-8f);
    }
    __syncthreads();
    float inv = w[0];
#pragma unroll
    for (int k = 0; k < 4; k++)
        g_embn[row * D + t + 256 * k] = __float2bfloat16(v[k] * inv);
}

// ---------------------------------------------------------------------------
// Kernel 2: label decode (int32 vs int64, detected from data), class counts,
// first-positive per row, zero accumulators (re-zeroed every graph replay).
// ---------------------------------------------------------------------------
__global__ void k_meta(const int* __restrict__ yraw) {
    __shared__ int sy[N];
    __shared__ int j0s[NCLS], j1s[NCLS];
    __shared__ int oddnz;
    int t = threadIdx.x;           // 256 threads

    if (t == 0) oddnz = 0;
    __syncthreads();
    int local = 0;
    for (int i = t; i < 2048; i += 256)
        if (yraw[2 * i + 1] != 0) local = 1;
    if (local) atomicOr(&oddnz, 1);
    __syncthreads();
    const bool is64 = (oddnz == 0);

    for (int i = t; i < N; i += 256) {
        int v = is64 ? yraw[2 * i] : yraw[i];
        sy[i] = v;
        g_y[i] = v;
    }
    __syncthreads();

    if (t < NCLS) {
        int c = t, cnt = 0, j0 = -1, j1 = -1;
        for (int i = 0; i < N; i++) {
            if (sy[i] == c) {
                cnt++;
                if (j0 < 0) j0 = i;
                else if (j1 < 0) j1 = i;
            }
        }
        g_cnt[c] = cnt; j0s[c] = j0; j1s[c] = j1;
    }
    __syncthreads();

    for (int i = t; i < N; i += 256) {
        int c = sy[i];
        g_firstpos[i] = (j0s[c] == i) ? j1s[c] : j0s[c];
        g_rowsum[i] = 0.0f;
        g_posval[i] = 0.0f;
    }
}

// ---------------------------------------------------------------------------
// Kernel 3: symmetric fused GEMM. Only upper-triangular block tiles (br<=bc).
// Off-diagonal blocks contribute exp(S) to BOTH row sums (rows of br-tile)
// and column sums (rows of bc-tile, via symmetry S_ij = S_ji).
// ---------------------------------------------------------------------------
__device__ __forceinline__ void mma16816(float c[4], const uint32_t a[4], const uint32_t b[2]) {
    asm volatile(
        "mma.sync.aligned.m16n8k16.row.col.f32.bf16.bf16.f32 "
        "{%0,%1,%2,%3}, {%4,%5,%6,%7}, {%8,%9}, {%0,%1,%2,%3};"
        : "+f"(c[0]), "+f"(c[1]), "+f"(c[2]), "+f"(c[3])
        : "r"(a[0]), "r"(a[1]), "r"(a[2]), "r"(a[3]), "r"(b[0]), "r"(b[1]));
}

__global__ void __launch_bounds__(256, 2) k_gemm() {
    __shared__ alignas(16) __nv_bfloat16 As[BM * SLD];
    __shared__ alignas(16) __nv_bfloat16 Bs[BN * SLD];
    __shared__ int ys_r[BM], ys_c[BN], fps_r[BM], fps_c[BN];
    __shared__ float rowacc[BM], colacc[BN];

    // map linear block id -> upper-triangular (br, bc)
    int rem = blockIdx.x;
    int br = 0;
    while (rem >= NT - br) { rem -= NT - br; br++; }
    const int bc = br + rem;
    const bool diag = (br == bc);

    const int tid = threadIdx.x;
    const int warp = tid >> 5, lane = tid & 31;
    const int wm = warp & 3, wn = warp >> 2;      // 4 warps along M, 2 along N
    const int g = lane >> 2, t4 = lane & 3;

    if (tid < 128) {
        ys_r[tid]  = g_y[br * BM + tid];
        ys_c[tid]  = g_y[bc * BN + tid];
        fps_r[tid] = g_firstpos[br * BM + tid];
        fps_c[tid] = g_firstpos[bc * BN + tid];
        rowacc[tid] = 0.0f;
        colacc[tid] = 0.0f;
    }

    float acc[2][8][4];
#pragma unroll
    for (int i = 0; i < 2; i++)
#pragma unroll
        for (int j = 0; j < 8; j++)
#pragma unroll
            for (int e = 0; e < 4; e++) acc[i][j][e] = 0.0f;

    // global load indexing: 512 uint4 per tile, 2 per thread
    const int li0 = tid, li1 = tid + 256;
    const int r0 = li0 >> 2, c0 = (li0 & 3) * 8;
    const int r1 = li1 >> 2, c1 = (li1 & 3) * 8;
    const __nv_bfloat16* gA = g_embn + (size_t)(br * BM) * D;
    const __nv_bfloat16* gB = g_embn + (size_t)(bc * BN) * D;

    for (int k0 = 0; k0 < D; k0 += BK) {
        uint4 a0 = *(const uint4*)(gA + (size_t)r0 * D + k0 + c0);
        uint4 a1 = *(const uint4*)(gA + (size_t)r1 * D + k0 + c1);
        uint4 b0 = *(const uint4*)(gB + (size_t)r0 * D + k0 + c0);
        uint4 b1 = *(const uint4*)(gB + (size_t)r1 * D + k0 + c1);
        __syncthreads();
        *(uint4*)(As + r0 * SLD + c0) = a0;
        *(uint4*)(As + r1 * SLD + c1) = a1;
        *(uint4*)(Bs + r0 * SLD + c0) = b0;
        *(uint4*)(Bs + r1 * SLD + c1) = b1;
        __syncthreads();

        const uint32_t* Aw = (const uint32_t*)As;   // word stride 20/row
        const uint32_t* Bw = (const uint32_t*)Bs;
#pragma unroll
        for (int kk = 0; kk < 2; kk++) {
            const int kw = kk * 8;   // 16 bf16 = 8 words
            uint32_t af[2][4], bf[8][2];
#pragma unroll
            for (int mf = 0; mf < 2; mf++) {
                int r = wm * 32 + mf * 16 + g;
                af[mf][0] = Aw[r * 20 + kw + t4];
                af[mf][1] = Aw[(r + 8) * 20 + kw + t4];
                af[mf][2] = Aw[r * 20 + kw + t4 + 4];
                af[mf][3] = Aw[(r + 8) * 20 + kw + t4 + 4];
            }
#pragma unroll
            for (int nf = 0; nf < 8; nf++) {
                int n = wn * 64 + nf * 8 + g;
                bf[nf][0] = Bw[n * 20 + kw + t4];
                bf[nf][1] = Bw[n * 20 + kw + t4 + 4];
            }
#pragma unroll
            for (int mf = 0; mf < 2; mf++)
#pragma unroll
                for (int nf = 0; nf < 8; nf++)
                    mma16816(acc[mf][nf], af[mf], bf[nf]);
        }
    }

    // ---- epilogue: S = (cos+1)*0.25; mask; exp; row (+col if offdiag) sums ----
    float colpart[8][2];
#pragma unroll
    for (int nf = 0; nf < 8; nf++) { colpart[nf][0] = 0.0f; colpart[nf][1] = 0.0f; }

#pragma unroll
    for (int mf = 0; mf < 2; mf++) {
#pragma unroll
        for (int h = 0; h < 2; h++) {
            const int lr = wm * 32 + mf * 16 + h * 8 + g;
            const int yi = ys_r[lr];
            const int fpi = fps_r[lr];
            const int gi = br * BM + lr;
            const int gr = br * BM + lr;   // global row index
            float sum = 0.0f;
#pragma unroll
            for (int nf = 0; nf < 8; nf++) {
#pragma unroll
                for (int e = 0; e < 2; e++) {
                    const int lc = wn * 64 + nf * 8 + t4 * 2 + e;
                    const float S = (acc[mf][nf][h * 2 + e] + 1.0f) * 0.25f;
                    float ev = (ys_c[lc] != yi) ? __expf(S) : 0.0f;
                    sum += ev;
                    if (!diag) colpart[nf][e] += ev;
                    if (bc * BN + lc == fpi) g_posval[gi] = S;       // row-side posval
                    if (!diag && gr == fps_c[lc])
                        g_posval[bc * BN + lc] = S;                  // mirrored posval
                }
            }
            sum += __shfl_xor_sync(0xffffffffu, sum, 1);
            sum += __shfl_xor_sync(0xffffffffu, sum, 2);
            if (t4 == 0) atomicAdd(&rowacc[lr], sum);
        }
    }

    if (!diag) {
        // reduce colpart over the g dimension (lanes differing in bits 2..4)
#pragma unroll
        for (int nf = 0; nf < 8; nf++) {
#pragma unroll
            for (int e = 0; e < 2; e++) {
                float v = colpart[nf][e];
                v += __shfl_xor_sync(0xffffffffu, v, 4);
                v += __shfl_xor_sync(0xffffffffu, v, 8);
                v += __shfl_xor_sync(0xffffffffu, v, 16);
                if (g == 0) {
                    const int lc = wn * 64 + nf * 8 + t4 * 2 + e;
                    atomicAdd(&colacc[lc], v);
                }
            }
        }
    }

    __syncthreads();
    if (tid < 128) {
        atomicAdd(&g_rowsum[br * BM + tid], rowacc[tid]);
        if (!diag) atomicAdd(&g_rowsum[bc * BN + tid], colacc[tid]);
    }
}

// ---------------------------------------------------------------------------
// Kernel 4: final per-row lse and scalar reduce
// lse_i = log(exp(pv) + rowsum + (8190 - num_neg)); num_neg = N - cnt[y_i]
// ---------------------------------------------------------------------------
__global__ void k_final(float* __restrict__ out) {
    int t = threadIdx.x;           // 1024 threads
    int lane = t & 31, warp = t >> 5;
    float local = 0.0f;
    for (int i = t; i < N; i += 1024) {
        float pv = g_posval[i];
        int cnt = g_cnt[g_y[i]];
        float zeros = (float)(2 * N - 2 - (N - cnt));  // 8190 - num_neg = 4094 + cnt
        float tot = expf(pv) + g_rowsum[i] + zeros;
        local += logf(tot) - pv;
    }
#pragma unroll
    for (int o = 16; o > 0; o >>= 1) local += __shfl_down_sync(0xffffffffu, local, o);
    __shared__ float red[32];
    if (lane == 0) red[warp] = local;
    __syncthreads();
    if (t < 32) {
        float v = red[t];
#pragma unroll
        for (int o = 16; o > 0; o >>= 1) v += __shfl_down_sync(0xffffffffu, v, o);
        if (t == 0) out[0] = v * (1.0f / (float)N);
    }
}

// ---------------------------------------------------------------------------
extern "C" void kernel_launch(void* const* d_in, const int* in_sizes, int n_in,
                              void* d_out, int out_size) {
    const float* emb = (const float*)d_in[0];
    const int* yraw = (const int*)d_in[1];   // int32 or int64; k_meta detects
    float* out = (float*)d_out;

    k_norm<<<N, 256>>>(emb);
    k_meta<<<1, 256>>>(yraw);
    k_gemm<<<NBLK, 256>>>();
    k_final<<<1, 1024>>>(out);
}

// round 7
// speedup vs baseline: 2.8403x; 2.1099x over previous
#include <cuda_runtime.h>
#include <cuda_bf16.h>
#include <stdint.h>

// Problem constants
#define N 4096
#define D 1024
#define NCLS 128

// GEMM tiling
#define BM 128
#define BN 128
#define BK 64                       // K per stage (128B/row)
#define NCHUNK (D / BK)             // 16
#define NT (N / BM)                 // 32
#define NBLK (NT * (NT + 1) / 2)    // 528 upper-triangular tiles
#define SLD2 72                     // bf16 stride (144B): conflict-free LDSM phases
#define ROWB 144                    // bytes per smem row
#define STAGE_BYTES (BM * ROWB)     // 18432 per operand
#define DYN_SMEM (2 * 2 * STAGE_BYTES + 128)

// Scratch (allocation-free: __device__ globals)
static __device__ __align__(16) __nv_bfloat16 g_embn[N * D];
static __device__ float g_rowsum[N];
static __device__ float g_posval[N];
static __device__ int   g_firstpos[N];
static __device__ int   g_cnt[NCLS];
static __device__ int   g_y[N];

// ---------------------------------------------------------------------------
// helpers
// ---------------------------------------------------------------------------
__device__ __forceinline__ uint32_t smem_u32(const void* p) {
    uint32_t a;
    asm("{ .reg .u64 t; cvta.to.shared.u64 t, %1; cvt.u32.u64 %0, t; }" : "=r"(a) : "l"(p));
    return a;
}
__device__ __forceinline__ void cpa16(uint32_t dst, const void* src) {
    asm volatile("cp.async.cg.shared.global [%0], [%1], 16;"
                 :: "r"(dst), "l"((unsigned long long)__cvta_generic_to_global(src)));
}
__device__ __forceinline__ void cpa_commit() { asm volatile("cp.async.commit_group;" ::: "memory"); }
template<int Nn> __device__ __forceinline__ void cpa_wait() {
    asm volatile("cp.async.wait_group %0;" :: "n"(Nn) : "memory");
}
__device__ __forceinline__ void ldsm4(uint32_t& r0, uint32_t& r1, uint32_t& r2, uint32_t& r3,
                                      uint32_t addr) {
    asm volatile("ldmatrix.sync.aligned.m8n8.x4.shared.b16 {%0,%1,%2,%3}, [%4];"
                 : "=r"(r0), "=r"(r1), "=r"(r2), "=r"(r3) : "r"(addr));
}
__device__ __forceinline__ void mma16816(float c[4], const uint32_t a[4], const uint32_t b[2]) {
    asm volatile(
        "mma.sync.aligned.m16n8k16.row.col.f32.bf16.bf16.f32 "
        "{%0,%1,%2,%3}, {%4,%5,%6,%7}, {%8,%9}, {%0,%1,%2,%3};"
        : "+f"(c[0]), "+f"(c[1]), "+f"(c[2]), "+f"(c[3])
        : "r"(a[0]), "r"(a[1]), "r"(a[2]), "r"(a[3]), "r"(b[0]), "r"(b[1]));
}

// ---------------------------------------------------------------------------
// Kernel 1: per-row L2 normalize, write bf16
// ---------------------------------------------------------------------------
__global__ void k_norm(const float* __restrict__ in) {
    int row = blockIdx.x;
    int t = threadIdx.x;           // 256 threads
    int lane = t & 31, warp = t >> 5;

    float v[4];
#pragma unroll
    for (int k = 0; k < 4; k++) v[k] = in[row * D + t + 256 * k];

    float ss = v[0]*v[0] + v[1]*v[1] + v[2]*v[2] + v[3]*v[3];
#pragma unroll
    for (int o = 16; o > 0; o >>= 1) ss += __shfl_down_sync(0xffffffffu, ss, o);

    __shared__ float w[8];
    if (lane == 0) w[warp] = ss;
    __syncthreads();
    if (t == 0) {
        float tot = 0.f;
#pragma unroll
        for (int i = 0; i < 8; i++) tot += w[i];
        w[0] = 1.0f / fmaxf(sqrtf(tot), 1e-8f);
    }
    __syncthreads();
    float inv = w[0];
#pragma unroll
    for (int k = 0; k < 4; k++)
        g_embn[row * D + t + 256 * k] = __float2bfloat16(v[k] * inv);
}

// ---------------------------------------------------------------------------
// Kernel 2: label decode (int32/int64 autodetect), class counts via smem
// atomics, first/second occurrence per class, zero accumulators each replay.
// ---------------------------------------------------------------------------
__global__ void k_meta(const int* __restrict__ yraw) {
    __shared__ int cnt_s[NCLS], j0s[NCLS], j1s[NCLS];
    __shared__ int oddnz;
    int t = threadIdx.x;           // 256 threads

    if (t == 0) oddnz = 0;
    if (t < NCLS) { cnt_s[t] = 0; j0s[t] = 0x7fffffff; j1s[t] = 0x7fffffff; }
    __syncthreads();
    int local = 0;
    for (int i = t; i < 2048; i += 256)
        if (yraw[2 * i + 1] != 0) local = 1;
    if (local) atomicOr(&oddnz, 1);
    __syncthreads();
    const bool is64 = (oddnz == 0);

    for (int i = t; i < N; i += 256) {
        int v = is64 ? yraw[2 * i] : yraw[i];
        g_y[i] = v;
        atomicAdd(&cnt_s[v], 1);
        atomicMin(&j0s[v], i);
    }
    __syncthreads();
    for (int i = t; i < N; i += 256) {
        int c = g_y[i];
        if (i != j0s[c]) atomicMin(&j1s[c], i);
    }
    __syncthreads();
    if (t < NCLS) g_cnt[t] = cnt_s[t];
    for (int i = t; i < N; i += 256) {
        int c = g_y[i];
        int j1 = (j1s[c] == 0x7fffffff) ? -1 : j1s[c];
        g_firstpos[i] = (j0s[c] == i) ? j1 : j0s[c];
        g_rowsum[i] = 0.0f;
        g_posval[i] = 0.0f;
    }
}

// ---------------------------------------------------------------------------
// Kernel 3: symmetric fused GEMM, cp.async double-buffered + ldmatrix frags.
// Upper-triangular block tiles; off-diagonal blocks scatter exp(S) into both
// row sums and (via symmetry) column sums.
// ---------------------------------------------------------------------------
__global__ void __launch_bounds__(256) k_gemm() {
    extern __shared__ char dynsm[];
    __shared__ int ys_r[BM], ys_c[BN], fps_r[BM], fps_c[BN];
    __shared__ float rowacc[BM], colacc[BN];

    // linear block id -> upper-triangular (br, bc)
    int rem = blockIdx.x, br = 0;
    while (rem >= NT - br) { rem -= NT - br; br++; }
    const int bc = br + rem;
    const bool diag = (br == bc);

    const int tid = threadIdx.x;
    const int warp = tid >> 5, lane = tid & 31;
    const int wm = warp & 3, wn = warp >> 2;      // 4 warps along M, 2 along N
    const int g = lane >> 2, t4 = lane & 3;

    if (tid < 128) {
        ys_r[tid]  = g_y[br * BM + tid];
        ys_c[tid]  = g_y[bc * BN + tid];
        fps_r[tid] = g_firstpos[br * BM + tid];
        fps_c[tid] = g_firstpos[bc * BN + tid];
        rowacc[tid] = 0.0f;
        colacc[tid] = 0.0f;
    }

    const uint32_t sb = (smem_u32(dynsm) + 127) & ~127u;
    const __nv_bfloat16* gA = g_embn + (size_t)(br * BM) * D;
    const __nv_bfloat16* gB = g_embn + (size_t)(bc * BN) * D;

    // stage fill: per operand 128 rows x 8 x 16B chunks = 1024, 4 per thread
    const int frow = tid >> 3, fseg = tid & 7;            // rows advance by 32/iter
    auto fill = [&](int s, int c) {
        const uint32_t ab = sb + s * 2 * STAGE_BYTES;
        const uint32_t bb = ab + STAGE_BYTES;
        const int k0 = c * BK;
#pragma unroll
        for (int j = 0; j < 4; j++) {
            const int row = frow + j * 32;
            const uint32_t dst = row * ROWB + fseg * 16;
            const size_t src = (size_t)row * D + k0 + fseg * 8;
            cpa16(ab + dst, gA + src);
            cpa16(bb + dst, gB + src);
        }
        cpa_commit();
    };

    float acc[2][8][4];
#pragma unroll
    for (int i = 0; i < 2; i++)
#pragma unroll
        for (int j = 0; j < 8; j++)
#pragma unroll
            for (int e = 0; e < 4; e++) acc[i][j][e] = 0.0f;

    fill(0, 0);
    fill(1, 1);

    // ldmatrix lane addressing: lanes 0-15 -> rows 0..15 (k bytes 0-15),
    // lanes 16-31 -> rows 0..15 (k bytes 16-31)
    const int lrow = lane & 15;
    const int khalf = (lane >> 4) * 16;
    const uint32_t aoff = (wm * 32 + lrow) * ROWB + khalf;
    const uint32_t boff = (wn * 64 + lrow) * ROWB + khalf;

    for (int c = 0; c < NCHUNK; c++) {
        const int s = c & 1;
        if (c == NCHUNK - 1) cpa_wait<0>(); else cpa_wait<1>();
        __syncthreads();                     // stage s ready, visible block-wide

        const uint32_t A0 = sb + s * 2 * STAGE_BYTES + aoff;
        const uint32_t B0 = sb + s * 2 * STAGE_BYTES + STAGE_BYTES + boff;
#pragma unroll
        for (int kk = 0; kk < 4; kk++) {
            const int kb = kk * 32;          // 16 bf16 = 32B per k-step
            uint32_t af[2][4], bfr[8][2];
            ldsm4(af[0][0], af[0][1], af[0][2], af[0][3], A0 + kb);
            ldsm4(af[1][0], af[1][1], af[1][2], af[1][3], A0 + 16 * ROWB + kb);
#pragma unroll
            for (int p = 0; p < 4; p++)      // each covers nf = 2p, 2p+1
                ldsm4(bfr[2*p][0], bfr[2*p+1][0], bfr[2*p][1], bfr[2*p+1][1],
                      B0 + p * 16 * ROWB + kb);
#pragma unroll
            for (int mf = 0; mf < 2; mf++)
#pragma unroll
                for (int nf = 0; nf < 8; nf++)
                    mma16816(acc[mf][nf], af[mf], bfr[nf]);
        }
        __syncthreads();                     // all warps done reading stage s
        if (c + 2 < NCHUNK) fill(s, c + 2);
    }

    // ---- epilogue: S = (cos+1)*0.25; mask; exp; row (+col if offdiag) sums ----
    float colpart[8][2];
#pragma unroll
    for (int nf = 0; nf < 8; nf++) { colpart[nf][0] = 0.0f; colpart[nf][1] = 0.0f; }

#pragma unroll
    for (int mf = 0; mf < 2; mf++) {
#pragma unroll
        for (int h = 0; h < 2; h++) {
            const int lr = wm * 32 + mf * 16 + h * 8 + g;
            const int yi = ys_r[lr];
            const int fpi = fps_r[lr];
            const int gr = br * BM + lr;
            float sum = 0.0f;
#pragma unroll
            for (int nf = 0; nf < 8; nf++) {
#pragma unroll
                for (int e = 0; e < 2; e++) {
                    const int lc = wn * 64 + nf * 8 + t4 * 2 + e;
                    const float S = (acc[mf][nf][h * 2 + e] + 1.0f) * 0.25f;
                    float ev = (ys_c[lc] != yi) ? __expf(S) : 0.0f;
                    sum += ev;
                    if (!diag) colpart[nf][e] += ev;
                    if (bc * BN + lc == fpi) g_posval[gr] = S;            // row-side
                    if (!diag && gr == fps_c[lc]) g_posval[bc * BN + lc] = S;  // mirror
                }
            }
            sum += __shfl_xor_sync(0xffffffffu, sum, 1);
            sum += __shfl_xor_sync(0xffffffffu, sum, 2);
            if (t4 == 0) atomicAdd(&rowacc[lr], sum);
        }
    }

    if (!diag) {
#pragma unroll
        for (int nf = 0; nf < 8; nf++) {
#pragma unroll
            for (int e = 0; e < 2; e++) {
                float v = colpart[nf][e];
                v += __shfl_xor_sync(0xffffffffu, v, 4);
                v += __shfl_xor_sync(0xffffffffu, v, 8);
                v += __shfl_xor_sync(0xffffffffu, v, 16);
                if (g == 0) {
                    const int lc = wn * 64 + nf * 8 + t4 * 2 + e;
                    atomicAdd(&colacc[lc], v);
                }
            }
        }
    }

    __syncthreads();
    if (tid < 128) {
        atomicAdd(&g_rowsum[br * BM + tid], rowacc[tid]);
        if (!diag) atomicAdd(&g_rowsum[bc * BN + tid], colacc[tid]);
    }
}

// ---------------------------------------------------------------------------
// Kernel 4: final per-row lse and scalar reduce
// lse_i = log(exp(pv) + rowsum + (4094 + cnt[y_i])); loss = mean(lse - pv)
// ---------------------------------------------------------------------------
__global__ void k_final(float* __restrict__ out) {
    int t = threadIdx.x;           // 1024 threads
    int lane = t & 31, warp = t >> 5;
    float local = 0.0f;
#pragma unroll
    for (int k = 0; k < N / 1024; k++) {
        int i = t + k * 1024;
        float pv = g_posval[i];
        float rs = g_rowsum[i];
        int cnt = g_cnt[g_y[i]];
        float tot = __expf(pv) + rs + (float)(4094 + cnt);
        local += __logf(tot) - pv;
    }
#pragma unroll
    for (int o = 16; o > 0; o >>= 1) local += __shfl_down_sync(0xffffffffu, local, o);
    __shared__ float red[32];
    if (lane == 0) red[warp] = local;
    __syncthreads();
    if (t < 32) {
        float v = red[t];
#pragma unroll
        for (int o = 16; o > 0; o >>= 1) v += __shfl_down_sync(0xffffffffu, v, o);
        if (t == 0) out[0] = v * (1.0f / (float)N);
    }
}

// ---------------------------------------------------------------------------
extern "C" void kernel_launch(void* const* d_in, const int* in_sizes, int n_in,
                              void* d_out, int out_size) {
    const float* emb = (const float*)d_in[0];
    const int* yraw = (const int*)d_in[1];   // int32 or int64; k_meta detects
    float* out = (float*)d_out;

    static int smem_set = 0;
    if (!smem_set) {
        cudaFuncSetAttribute(k_gemm, cudaFuncAttributeMaxDynamicSharedMemorySize, DYN_SMEM);
        smem_set = 1;
    }

    k_norm<<<N, 256>>>(emb);
    k_meta<<<1, 256>>>(yraw);
    k_gemm<<<NBLK, 256, DYN_SMEM>>>();
    k_final<<<1, 1024>>>(out);
}